// round 5
// baseline (speedup 1.0000x reference)
#include <cuda_runtime.h>
#include <cuda_bf16.h>
#include <math.h>

// Problem constants
#define B 8
#define T 2048
#define D 1024
#define HS 64
#define BT (B*T)            // 16384 rows

// Scratch for Q,K,V projections: [B*T][HS] each, 4 MB each (device globals: allocation-free)
__device__ float g_Q[BT * HS];
__device__ float g_K[BT * HS];
__device__ float g_V[BT * HS];

// ---------------------------------------------------------------------------
// Kernel 1: fused QKV projection.
// Each block computes 64 rows of Q,K,V.  x tile [64,32] staged once per k-step
// and reused against Wq/Wk/Wv tiles [32,64].  Thread t owns output column
// (t&63) and 16 rows ((t>>6)*16 ..), accumulating all three projections.
// ---------------------------------------------------------------------------
__global__ __launch_bounds__(256, 2)
void qkv_kernel(const float* __restrict__ x,
                const float* __restrict__ Wq, const float* __restrict__ bq,
                const float* __restrict__ Wk, const float* __restrict__ bk,
                const float* __restrict__ Wv, const float* __restrict__ bv)
{
    __shared__ __align__(16) float xs[64][36];   // pitch 36: float4-aligned
    __shared__ float wqs[32][64];
    __shared__ float wks[32][64];
    __shared__ float wvs[32][64];

    const int t   = threadIdx.x;
    const int r0  = blockIdx.x * 64;
    const int col = t & 63;
    const int rg  = t >> 6;          // 0..3 -> row group of 16

    float acc0[16], acc1[16], acc2[16];
#pragma unroll
    for (int r = 0; r < 16; r++) { acc0[r] = 0.f; acc1[r] = 0.f; acc2[r] = 0.f; }

    for (int k0 = 0; k0 < D; k0 += 32) {
        // load x tile [64][32] (coalesced 128B rows)
#pragma unroll
        for (int i = 0; i < 8; i++) {
            int idx = t + 256 * i;
            int rr = idx >> 5, cc = idx & 31;
            xs[rr][cc] = x[(size_t)(r0 + rr) * D + k0 + cc];
        }
        // load W tiles [32][64]
#pragma unroll
        for (int i = 0; i < 8; i++) {
            int idx = t + 256 * i;
            int rr = idx >> 6, cc = idx & 63;
            wqs[rr][cc] = Wq[(k0 + rr) * HS + cc];
            wks[rr][cc] = Wk[(k0 + rr) * HS + cc];
            wvs[rr][cc] = Wv[(k0 + rr) * HS + cc];
        }
        __syncthreads();

#pragma unroll
        for (int kk = 0; kk < 32; kk += 4) {
            float wq[4], wk4[4], wv4[4];
#pragma unroll
            for (int u = 0; u < 4; u++) {
                wq[u]  = wqs[kk + u][col];
                wk4[u] = wks[kk + u][col];
                wv4[u] = wvs[kk + u][col];
            }
#pragma unroll
            for (int r = 0; r < 16; r++) {
                const float4 xv = *(const float4*)&xs[rg * 16 + r][kk];
                acc0[r] = fmaf(xv.x, wq[0],  acc0[r]);
                acc0[r] = fmaf(xv.y, wq[1],  acc0[r]);
                acc0[r] = fmaf(xv.z, wq[2],  acc0[r]);
                acc0[r] = fmaf(xv.w, wq[3],  acc0[r]);
                acc1[r] = fmaf(xv.x, wk4[0], acc1[r]);
                acc1[r] = fmaf(xv.y, wk4[1], acc1[r]);
                acc1[r] = fmaf(xv.z, wk4[2], acc1[r]);
                acc1[r] = fmaf(xv.w, wk4[3], acc1[r]);
                acc2[r] = fmaf(xv.x, wv4[0], acc2[r]);
                acc2[r] = fmaf(xv.y, wv4[1], acc2[r]);
                acc2[r] = fmaf(xv.z, wv4[2], acc2[r]);
                acc2[r] = fmaf(xv.w, wv4[3], acc2[r]);
            }
        }
        __syncthreads();
    }

    const float bqv = bq[col], bkv = bk[col], bvv = bv[col];
#pragma unroll
    for (int r = 0; r < 16; r++) {
        int row = r0 + rg * 16 + r;
        g_Q[(size_t)row * HS + col] = acc0[r] + bqv;
        g_K[(size_t)row * HS + col] = acc1[r] + bkv;
        g_V[(size_t)row * HS + col] = acc2[r] + bvv;
    }
}

// ---------------------------------------------------------------------------
// Kernel 2: causal flash attention (fp32).
// Grid (16, B).  Each block processes two q-tiles {x, 31-x} sequentially so
// every block does exactly 33 k-tiles (causal load balance).
// Per q-tile: online softmax over 64-wide k-tiles.
// smem pitch 66 (even, non-multiple-of-32): float2 loads stay 8B-aligned and
// both QK^T and PV phases are shared-memory bank-conflict free.
// ---------------------------------------------------------------------------
#define PITCH 66
#define NQT (T / 64)   // 32 q-tiles

__global__ __launch_bounds__(256, 1)
void attn_kernel(float* __restrict__ out)
{
    extern __shared__ __align__(16) float sm[];
    float* Qs  = sm;                    // 64*66
    float* Ks  = Qs + 64 * PITCH;       // 64*66
    float* Vs  = Ks + 64 * PITCH;       // 64*66
    float* Ps  = Vs + 64 * PITCH;       // 64*66
    float* m_s = Ps + 64 * PITCH;       // 64
    float* l_s = m_s + 64;              // 64
    float* c_s = l_s + 64;              // 64

    const int t      = threadIdx.x;
    const int b      = blockIdx.y;
    const int qr0    = (t >> 4) << 2;   // 4 consecutive q-rows per thread
    const int lane16 = t & 15;          // column group: {lane16 + 16j}
    const int row    = t >> 2;          // softmax: 4 threads per row
    const int sub    = t & 3;

    for (int pass = 0; pass < 2; pass++) {
        const int qt = pass ? (NQT - 1 - (int)blockIdx.x) : (int)blockIdx.x;
        const int q0 = qt * 64;

        __syncthreads();   // protect smem state from previous pass epilogue

        // load Q tile and init state
#pragma unroll
        for (int i = 0; i < 16; i++) {
            int idx = t + 256 * i;
            int rr = idx >> 6, cc = idx & 63;
            Qs[rr * PITCH + cc] = g_Q[((size_t)b * T + q0 + rr) * HS + cc];
        }
        if (t < 64) { m_s[t] = -1e30f; l_s[t] = 0.f; }

        float o[4][4];
#pragma unroll
        for (int r = 0; r < 4; r++)
#pragma unroll
            for (int j = 0; j < 4; j++) o[r][j] = 0.f;

        for (int kt = 0; kt <= qt; kt++) {
            // --- load K,V tiles ---
#pragma unroll
            for (int i = 0; i < 16; i++) {
                int idx = t + 256 * i;
                int rr = idx >> 6, cc = idx & 63;
                size_t g = ((size_t)b * T + kt * 64 + rr) * HS + cc;
                Ks[rr * PITCH + cc] = g_K[g];
                Vs[rr * PITCH + cc] = g_V[g];
            }
            __syncthreads();

            // --- S = Q K^T (4x4 register tile, float2 over h) ---
            float s[4][4];
#pragma unroll
            for (int r = 0; r < 4; r++)
#pragma unroll
                for (int j = 0; j < 4; j++) s[r][j] = 0.f;

#pragma unroll
            for (int h = 0; h < HS; h += 2) {
                float2 qv[4], kv[4];
#pragma unroll
                for (int r = 0; r < 4; r++)
                    qv[r] = *(const float2*)&Qs[(qr0 + r) * PITCH + h];
#pragma unroll
                for (int j = 0; j < 4; j++)
                    kv[j] = *(const float2*)&Ks[(lane16 + 16 * j) * PITCH + h];
#pragma unroll
                for (int r = 0; r < 4; r++)
#pragma unroll
                    for (int j = 0; j < 4; j++) {
                        s[r][j] = fmaf(qv[r].x, kv[j].x, s[r][j]);
                        s[r][j] = fmaf(qv[r].y, kv[j].y, s[r][j]);
                    }
            }

            // scale + causal mask + stage to smem
            const bool diag = (kt == qt);
#pragma unroll
            for (int r = 0; r < 4; r++)
#pragma unroll
                for (int j = 0; j < 4; j++) {
                    int kc = lane16 + 16 * j;
                    float v = s[r][j] * 0.125f;   // 1/sqrt(64)
                    if (diag && kc > qr0 + r) v = -1e30f;
                    Ps[(qr0 + r) * PITCH + kc] = v;
                }
            __syncthreads();

            // --- online softmax: 4 threads per row ---
            float tm = -1e30f;
#pragma unroll
            for (int i = 0; i < 16; i++)
                tm = fmaxf(tm, Ps[row * PITCH + sub * 16 + i]);
            tm = fmaxf(tm, __shfl_xor_sync(0xffffffffu, tm, 1));
            tm = fmaxf(tm, __shfl_xor_sync(0xffffffffu, tm, 2));

            float m_old = m_s[row];
            float m_new = fmaxf(m_old, tm);
            float ts = 0.f;
#pragma unroll
            for (int i = 0; i < 16; i++) {
                float p = __expf(Ps[row * PITCH + sub * 16 + i] - m_new);
                Ps[row * PITCH + sub * 16 + i] = p;
                ts += p;
            }
            ts += __shfl_xor_sync(0xffffffffu, ts, 1);
            ts += __shfl_xor_sync(0xffffffffu, ts, 2);
            float corr = __expf(m_old - m_new);
            if (sub == 0) {
                m_s[row] = m_new;
                l_s[row] = l_s[row] * corr + ts;
                c_s[row] = corr;
            }
            __syncthreads();

            // --- O = O*corr + P V ---
#pragma unroll
            for (int r = 0; r < 4; r++) {
                float cr = c_s[qr0 + r];
#pragma unroll
                for (int j = 0; j < 4; j++) o[r][j] *= cr;
            }
#pragma unroll
            for (int kc = 0; kc < 64; kc += 2) {
                float2 pv[4];
                float vv0[4], vv1[4];
#pragma unroll
                for (int r = 0; r < 4; r++)
                    pv[r] = *(const float2*)&Ps[(qr0 + r) * PITCH + kc];
#pragma unroll
                for (int j = 0; j < 4; j++) {
                    vv0[j] = Vs[kc * PITCH + lane16 + 16 * j];
                    vv1[j] = Vs[(kc + 1) * PITCH + lane16 + 16 * j];
                }
#pragma unroll
                for (int r = 0; r < 4; r++)
#pragma unroll
                    for (int j = 0; j < 4; j++) {
                        o[r][j] = fmaf(pv[r].x, vv0[j], o[r][j]);
                        o[r][j] = fmaf(pv[r].y, vv1[j], o[r][j]);
                    }
            }
            __syncthreads();  // Ks/Vs/Ps reused next tile
        }

        // epilogue: normalize and store
#pragma unroll
        for (int r = 0; r < 4; r++) {
            float inv = 1.0f / l_s[qr0 + r];
#pragma unroll
            for (int j = 0; j < 4; j++) {
                out[((size_t)b * T + q0 + qr0 + r) * HS + lane16 + 16 * j] = o[r][j] * inv;
            }
        }
    }
}

// ---------------------------------------------------------------------------
extern "C" void kernel_launch(void* const* d_in, const int* in_sizes, int n_in,
                              void* d_out, int out_size)
{
    const float* x  = (const float*)d_in[0];
    const float* Wq = (const float*)d_in[1];
    const float* bq = (const float*)d_in[2];
    const float* Wk = (const float*)d_in[3];
    const float* bk = (const float*)d_in[4];
    const float* Wv = (const float*)d_in[5];
    const float* bv = (const float*)d_in[6];
    float* out = (float*)d_out;

    qkv_kernel<<<BT / 64, 256>>>(x, Wq, bq, Wk, bk, Wv, bv);

    const int smem_bytes = (4 * 64 * PITCH + 3 * 64) * (int)sizeof(float); // ~67 KB
    cudaFuncSetAttribute(attn_kernel, cudaFuncAttributeMaxDynamicSharedMemorySize, smem_bytes);
    attn_kernel<<<dim3(NQT / 2, B), 256, smem_bytes>>>(out);
}

// round 11
// speedup vs baseline: 1.4707x; 1.4707x over previous
#include <cuda_runtime.h>
#include <cuda_bf16.h>
#include <math.h>
#include <stdint.h>

// Problem constants
#define B 8
#define T 2048
#define D 1024
#define HS 64
#define BT (B*T)            // 16384 rows

// Scratch
__device__ float g_Q[BT * HS];
__device__ float g_K[BT * HS];
__device__ float g_V[BT * HS];
// W transposed + split: rows n = 0..191 (Q:0-63, K:64-127, V:128-191), cols k = 0..1023
__device__ __nv_bfloat16 g_Whi[3 * HS * D];
__device__ __nv_bfloat16 g_Wlo[3 * HS * D];

// ===========================================================================
// mma.sync / ldmatrix helpers (base sm_80+ ISA — works on plain sm_103 target)
// ===========================================================================
__device__ __forceinline__ uint32_t smem_u32(const void* p) {
    uint32_t a;
    asm("{ .reg .u64 t; cvta.to.shared.u64 t, %1; cvt.u32.u64 %0, t; }" : "=r"(a) : "l"(p));
    return a;
}
__device__ __forceinline__ void ldmatrix_x4(uint32_t* r, uint32_t addr) {
    asm volatile("ldmatrix.sync.aligned.m8n8.x4.shared.b16 {%0,%1,%2,%3}, [%4];"
        : "=r"(r[0]), "=r"(r[1]), "=r"(r[2]), "=r"(r[3]) : "r"(addr));
}
__device__ __forceinline__ void ldmatrix_x2(uint32_t* r, uint32_t addr) {
    asm volatile("ldmatrix.sync.aligned.m8n8.x2.shared.b16 {%0,%1}, [%2];"
        : "=r"(r[0]), "=r"(r[1]) : "r"(addr));
}
__device__ __forceinline__ void mma_bf16(float* d, const uint32_t* a, const uint32_t* b) {
    asm volatile("mma.sync.aligned.m16n8k16.row.col.f32.bf16.bf16.f32 "
        "{%0,%1,%2,%3}, {%4,%5,%6,%7}, {%8,%9}, {%0,%1,%2,%3};"
        : "+f"(d[0]), "+f"(d[1]), "+f"(d[2]), "+f"(d[3])
        : "r"(a[0]), "r"(a[1]), "r"(a[2]), "r"(a[3]), "r"(b[0]), "r"(b[1]));
}

// ---------------------------------------------------------------------------
// Kernel 0: split W (fp32 [D][HS] x3) into transposed bf16 hi/lo [3*HS][D]
// ---------------------------------------------------------------------------
__global__ void wsplit_kernel(const float* __restrict__ Wq,
                              const float* __restrict__ Wk,
                              const float* __restrict__ Wv)
{
    int idx = blockIdx.x * 256 + threadIdx.x;     // 0 .. 3*64*1024-1
    if (idx >= 3 * HS * D) return;
    int m = idx >> 16;
    int n = (idx >> 10) & 63;
    int k = idx & 1023;
    const float* W = (m == 0) ? Wq : (m == 1) ? Wk : Wv;
    float v = W[k * HS + n];
    __nv_bfloat16 hi = __float2bfloat16_rn(v);
    __nv_bfloat16 lo = __float2bfloat16_rn(v - __bfloat162float(hi));
    g_Whi[idx] = hi;
    g_Wlo[idx] = lo;
}

// ---------------------------------------------------------------------------
// Kernel 1: QKV projection via mma.sync bf16 (3x-bf16 split: hh + hl + lh).
// CTA: 512 threads (16 warps, 4M x 4N), output 128 rows x 192 cols (Q|K|V).
// K staged in smem chunks of 64, row pitch 144B (ldmatrix conflict-free).
// ---------------------------------------------------------------------------
#define QPITCH 144                     // 64 bf16 (128B) + 16B pad
#define SMX_HI 0
#define SMX_LO (128 * QPITCH)          // 18432
#define SMW_HI (2 * 128 * QPITCH)      // 36864
#define SMW_LO (SMW_HI + 192 * QPITCH) // 64512
#define SM_QKV_TOTAL (SMW_LO + 192 * QPITCH)  // 92160

__global__ __launch_bounds__(512, 1)
void qkv_mma_kernel(const float* __restrict__ x,
                    const float* __restrict__ bq,
                    const float* __restrict__ bk,
                    const float* __restrict__ bv)
{
    extern __shared__ __align__(16) char smem[];
    const uint32_t sb = smem_u32(smem);
    const int t  = threadIdx.x;
    const int l  = t & 31;
    const int w  = t >> 5;      // 0..15
    const int wm = w >> 2;      // 0..3  (rows:  wm*32 .. +32)
    const int wn = w & 3;       // 0..3  (cols:  wn*48 .. +48)
    const int row0 = blockIdx.x * 128;

    float C[12][4];             // [mt*6+nt][4]
#pragma unroll
    for (int i = 0; i < 12; i++)
#pragma unroll
        for (int j = 0; j < 4; j++) C[i][j] = 0.f;

    // ldmatrix per-lane address offsets (within a tile base)
    const uint32_t aoff = (uint32_t)((wm * 32 + (l & 15)) * QPITCH + (l >> 4) * 16);
    const uint32_t boff = (uint32_t)((wn * 48 + (l & 7)) * QPITCH + ((l >> 3) & 1) * 16);

    for (int ci = 0; ci < 16; ci++) {
        const int k0 = ci * 64;
        __syncthreads();   // drain reads of previous chunk before overwrite

        // ---- stage x chunk [128 x 64] fp32 -> bf16 hi/lo, pitch 144B ----
#pragma unroll
        for (int i = 0; i < 8; i++) {
            int p  = t + 512 * i;            // 4096 pairs
            int r  = p >> 5;
            int cp = p & 31;
            float2 v = *(const float2*)&x[(size_t)(row0 + r) * D + k0 + 2 * cp];
            __nv_bfloat16 hx = __float2bfloat16_rn(v.x);
            __nv_bfloat16 hy = __float2bfloat16_rn(v.y);
            __nv_bfloat16 lx = __float2bfloat16_rn(v.x - __bfloat162float(hx));
            __nv_bfloat16 ly = __float2bfloat16_rn(v.y - __bfloat162float(hy));
            uint32_t hp = ((uint32_t)__bfloat16_as_ushort(hy) << 16) | __bfloat16_as_ushort(hx);
            uint32_t lp = ((uint32_t)__bfloat16_as_ushort(ly) << 16) | __bfloat16_as_ushort(lx);
            *(uint32_t*)(smem + SMX_HI + r * QPITCH + cp * 4) = hp;
            *(uint32_t*)(smem + SMX_LO + r * QPITCH + cp * 4) = lp;
        }
        // ---- stage W chunk [192 x 64] bf16 hi/lo ----
#pragma unroll
        for (int i = 0; i < 12; i++) {
            int p  = t + 512 * i;            // 6144 pairs
            int r  = p >> 5;                 // 0..191
            int kp = p & 31;
            uint32_t hp = *(const uint32_t*)&g_Whi[(size_t)r * D + k0 + 2 * kp];
            uint32_t lp = *(const uint32_t*)&g_Wlo[(size_t)r * D + k0 + 2 * kp];
            *(uint32_t*)(smem + SMW_HI + r * QPITCH + kp * 4) = hp;
            *(uint32_t*)(smem + SMW_LO + r * QPITCH + kp * 4) = lp;
        }
        __syncthreads();

        // ---- 4 k-steps of 16; products hh, hl, lh ----
#pragma unroll
        for (int ks = 0; ks < 4; ks++) {
            const uint32_t kso = ks * 32;
            uint32_t a[2][4], b[6][2];

            // A = x_hi
            ldmatrix_x4(a[0], sb + SMX_HI + aoff + kso);
            ldmatrix_x4(a[1], sb + SMX_HI + aoff + 16 * QPITCH + kso);
            // product hh
#pragma unroll
            for (int nt = 0; nt < 6; nt++)
                ldmatrix_x2(b[nt], sb + SMW_HI + boff + nt * 8 * QPITCH + kso);
#pragma unroll
            for (int mt = 0; mt < 2; mt++)
#pragma unroll
                for (int nt = 0; nt < 6; nt++) mma_bf16(C[mt * 6 + nt], a[mt], b[nt]);
            // product hl (A hi stays)
#pragma unroll
            for (int nt = 0; nt < 6; nt++)
                ldmatrix_x2(b[nt], sb + SMW_LO + boff + nt * 8 * QPITCH + kso);
#pragma unroll
            for (int mt = 0; mt < 2; mt++)
#pragma unroll
                for (int nt = 0; nt < 6; nt++) mma_bf16(C[mt * 6 + nt], a[mt], b[nt]);
            // product lh
            ldmatrix_x4(a[0], sb + SMX_LO + aoff + kso);
            ldmatrix_x4(a[1], sb + SMX_LO + aoff + 16 * QPITCH + kso);
#pragma unroll
            for (int nt = 0; nt < 6; nt++)
                ldmatrix_x2(b[nt], sb + SMW_HI + boff + nt * 8 * QPITCH + kso);
#pragma unroll
            for (int mt = 0; mt < 2; mt++)
#pragma unroll
                for (int nt = 0; nt < 6; nt++) mma_bf16(C[mt * 6 + nt], a[mt], b[nt]);
        }
    }

    // ---- epilogue: C layout d0,d1 = (row=l>>2, col=(l&3)*2,+1), d2,d3 = row+8 ----
#pragma unroll
    for (int nt = 0; nt < 6; nt++) {
        const int gn  = wn * 48 + nt * 8;
        const int mtx = gn >> 6;
        const float* bias = (mtx == 0) ? bq : (mtx == 1) ? bk : bv;
        float* dst        = (mtx == 0) ? g_Q : (mtx == 1) ? g_K : g_V;
        const int cn = (gn & 63) + (l & 3) * 2;
        const float b0 = bias[cn], b1 = bias[cn + 1];
#pragma unroll
        for (int mt = 0; mt < 2; mt++) {
            const int r = row0 + wm * 32 + mt * 16 + (l >> 2);
            float* p0 = &dst[(size_t)r * HS + cn];
            p0[0] = C[mt * 6 + nt][0] + b0;
            p0[1] = C[mt * 6 + nt][1] + b1;
            float* p1 = &dst[(size_t)(r + 8) * HS + cn];
            p1[0] = C[mt * 6 + nt][2] + b0;
            p1[1] = C[mt * 6 + nt][3] + b1;
        }
    }
}

// ---------------------------------------------------------------------------
// Kernel 2: causal flash attention (fp32) — unchanged from passing baseline.
// ---------------------------------------------------------------------------
#define PITCH 66
#define NQT (T / 64)   // 32 q-tiles

__global__ __launch_bounds__(256, 1)
void attn_kernel(float* __restrict__ out)
{
    extern __shared__ __align__(16) float sm[];
    float* Qs  = sm;
    float* Ks  = Qs + 64 * PITCH;
    float* Vs  = Ks + 64 * PITCH;
    float* Ps  = Vs + 64 * PITCH;
    float* m_s = Ps + 64 * PITCH;
    float* l_s = m_s + 64;
    float* c_s = l_s + 64;

    const int t      = threadIdx.x;
    const int b      = blockIdx.y;
    const int qr0    = (t >> 4) << 2;
    const int lane16 = t & 15;
    const int row    = t >> 2;
    const int sub    = t & 3;

    for (int pass = 0; pass < 2; pass++) {
        const int qt = pass ? (NQT - 1 - (int)blockIdx.x) : (int)blockIdx.x;
        const int q0 = qt * 64;

        __syncthreads();

#pragma unroll
        for (int i = 0; i < 16; i++) {
            int idx = t + 256 * i;
            int rr = idx >> 6, cc = idx & 63;
            Qs[rr * PITCH + cc] = g_Q[((size_t)b * T + q0 + rr) * HS + cc];
        }
        if (t < 64) { m_s[t] = -1e30f; l_s[t] = 0.f; }

        float o[4][4];
#pragma unroll
        for (int r = 0; r < 4; r++)
#pragma unroll
            for (int j = 0; j < 4; j++) o[r][j] = 0.f;

        for (int kt = 0; kt <= qt; kt++) {
#pragma unroll
            for (int i = 0; i < 16; i++) {
                int idx = t + 256 * i;
                int rr = idx >> 6, cc = idx & 63;
                size_t g = ((size_t)b * T + kt * 64 + rr) * HS + cc;
                Ks[rr * PITCH + cc] = g_K[g];
                Vs[rr * PITCH + cc] = g_V[g];
            }
            __syncthreads();

            float s[4][4];
#pragma unroll
            for (int r = 0; r < 4; r++)
#pragma unroll
                for (int j = 0; j < 4; j++) s[r][j] = 0.f;

#pragma unroll
            for (int h = 0; h < HS; h += 2) {
                float2 qv[4], kv[4];
#pragma unroll
                for (int r = 0; r < 4; r++)
                    qv[r] = *(const float2*)&Qs[(qr0 + r) * PITCH + h];
#pragma unroll
                for (int j = 0; j < 4; j++)
                    kv[j] = *(const float2*)&Ks[(lane16 + 16 * j) * PITCH + h];
#pragma unroll
                for (int r = 0; r < 4; r++)
#pragma unroll
                    for (int j = 0; j < 4; j++) {
                        s[r][j] = fmaf(qv[r].x, kv[j].x, s[r][j]);
                        s[r][j] = fmaf(qv[r].y, kv[j].y, s[r][j]);
                    }
            }

            const bool diag = (kt == qt);
#pragma unroll
            for (int r = 0; r < 4; r++)
#pragma unroll
                for (int j = 0; j < 4; j++) {
                    int kc = lane16 + 16 * j;
                    float v = s[r][j] * 0.125f;
                    if (diag && kc > qr0 + r) v = -1e30f;
                    Ps[(qr0 + r) * PITCH + kc] = v;
                }
            __syncthreads();

            float tm = -1e30f;
#pragma unroll
            for (int i = 0; i < 16; i++)
                tm = fmaxf(tm, Ps[row * PITCH + sub * 16 + i]);
            tm = fmaxf(tm, __shfl_xor_sync(0xffffffffu, tm, 1));
            tm = fmaxf(tm, __shfl_xor_sync(0xffffffffu, tm, 2));

            float m_old = m_s[row];
            float m_new = fmaxf(m_old, tm);
            float ts = 0.f;
#pragma unroll
            for (int i = 0; i < 16; i++) {
                float p = __expf(Ps[row * PITCH + sub * 16 + i] - m_new);
                Ps[row * PITCH + sub * 16 + i] = p;
                ts += p;
            }
            ts += __shfl_xor_sync(0xffffffffu, ts, 1);
            ts += __shfl_xor_sync(0xffffffffu, ts, 2);
            float corr = __expf(m_old - m_new);
            if (sub == 0) {
                m_s[row] = m_new;
                l_s[row] = l_s[row] * corr + ts;
                c_s[row] = corr;
            }
            __syncthreads();

#pragma unroll
            for (int r = 0; r < 4; r++) {
                float cr = c_s[qr0 + r];
#pragma unroll
                for (int j = 0; j < 4; j++) o[r][j] *= cr;
            }
#pragma unroll
            for (int kc = 0; kc < 64; kc += 2) {
                float2 pv[4];
                float vv0[4], vv1[4];
#pragma unroll
                for (int r = 0; r < 4; r++)
                    pv[r] = *(const float2*)&Ps[(qr0 + r) * PITCH + kc];
#pragma unroll
                for (int j = 0; j < 4; j++) {
                    vv0[j] = Vs[kc * PITCH + lane16 + 16 * j];
                    vv1[j] = Vs[(kc + 1) * PITCH + lane16 + 16 * j];
                }
#pragma unroll
                for (int r = 0; r < 4; r++)
#pragma unroll
                    for (int j = 0; j < 4; j++) {
                        o[r][j] = fmaf(pv[r].x, vv0[j], o[r][j]);
                        o[r][j] = fmaf(pv[r].y, vv1[j], o[r][j]);
                    }
            }
            __syncthreads();
        }

#pragma unroll
        for (int r = 0; r < 4; r++) {
            float inv = 1.0f / l_s[qr0 + r];
#pragma unroll
            for (int j = 0; j < 4; j++) {
                out[((size_t)b * T + q0 + qr0 + r) * HS + lane16 + 16 * j] = o[r][j] * inv;
            }
        }
    }
}

// ---------------------------------------------------------------------------
extern "C" void kernel_launch(void* const* d_in, const int* in_sizes, int n_in,
                              void* d_out, int out_size)
{
    const float* x  = (const float*)d_in[0];
    const float* Wq = (const float*)d_in[1];
    const float* bq = (const float*)d_in[2];
    const float* Wk = (const float*)d_in[3];
    const float* bk = (const float*)d_in[4];
    const float* Wv = (const float*)d_in[5];
    const float* bv = (const float*)d_in[6];
    float* out = (float*)d_out;

    wsplit_kernel<<<(3 * HS * D + 255) / 256, 256>>>(Wq, Wk, Wv);

    cudaFuncSetAttribute(qkv_mma_kernel, cudaFuncAttributeMaxDynamicSharedMemorySize, SM_QKV_TOTAL);
    qkv_mma_kernel<<<BT / 128, 512, SM_QKV_TOTAL>>>(x, bq, bk, bv);

    const int attn_smem = (4 * 64 * PITCH + 3 * 64) * (int)sizeof(float);
    cudaFuncSetAttribute(attn_kernel, cudaFuncAttributeMaxDynamicSharedMemorySize, attn_smem);
    attn_kernel<<<dim3(NQT / 2, B), 256, attn_smem>>>(out);
}

// round 17
// speedup vs baseline: 2.2335x; 1.5186x over previous
#include <cuda_runtime.h>
#include <cuda_bf16.h>
#include <math.h>
#include <stdint.h>

// Problem constants
#define B 8
#define T 2048
#define D 1024
#define HS 64
#define BT (B*T)            // 16384 rows

// bf16 hi/lo split Q,K,V (written by qkv kernel, read by attn kernel)
__device__ __nv_bfloat16 g_Qhi[BT * HS];
__device__ __nv_bfloat16 g_Qlo[BT * HS];
__device__ __nv_bfloat16 g_Khi[BT * HS];
__device__ __nv_bfloat16 g_Klo[BT * HS];
__device__ __nv_bfloat16 g_Vhi[BT * HS];
__device__ __nv_bfloat16 g_Vlo[BT * HS];
// W transposed + split: rows n = 0..191 (Q:0-63, K:64-127, V:128-191), k = 0..1023
__device__ __nv_bfloat16 g_Whi[3 * HS * D];
__device__ __nv_bfloat16 g_Wlo[3 * HS * D];

// ===========================================================================
// mma.sync / ldmatrix helpers (base sm_80+ ISA)
// ===========================================================================
__device__ __forceinline__ uint32_t smem_u32(const void* p) {
    uint32_t a;
    asm("{ .reg .u64 t; cvta.to.shared.u64 t, %1; cvt.u32.u64 %0, t; }" : "=r"(a) : "l"(p));
    return a;
}
__device__ __forceinline__ void ldmatrix_x4(uint32_t* r, uint32_t addr) {
    asm volatile("ldmatrix.sync.aligned.m8n8.x4.shared.b16 {%0,%1,%2,%3}, [%4];"
        : "=r"(r[0]), "=r"(r[1]), "=r"(r[2]), "=r"(r[3]) : "r"(addr));
}
__device__ __forceinline__ void ldmatrix_x2(uint32_t* r, uint32_t addr) {
    asm volatile("ldmatrix.sync.aligned.m8n8.x2.shared.b16 {%0,%1}, [%2];"
        : "=r"(r[0]), "=r"(r[1]) : "r"(addr));
}
__device__ __forceinline__ void ldmatrix_x2_trans(uint32_t* r, uint32_t addr) {
    asm volatile("ldmatrix.sync.aligned.m8n8.x2.trans.shared.b16 {%0,%1}, [%2];"
        : "=r"(r[0]), "=r"(r[1]) : "r"(addr));
}
__device__ __forceinline__ void mma_bf16(float* d, const uint32_t* a, const uint32_t* b) {
    asm volatile("mma.sync.aligned.m16n8k16.row.col.f32.bf16.bf16.f32 "
        "{%0,%1,%2,%3}, {%4,%5,%6,%7}, {%8,%9}, {%0,%1,%2,%3};"
        : "+f"(d[0]), "+f"(d[1]), "+f"(d[2]), "+f"(d[3])
        : "r"(a[0]), "r"(a[1]), "r"(a[2]), "r"(a[3]), "r"(b[0]), "r"(b[1]));
}
__device__ __forceinline__ uint32_t pack_bf16x2(float x, float y) {
    __nv_bfloat16 hx = __float2bfloat16_rn(x);
    __nv_bfloat16 hy = __float2bfloat16_rn(y);
    return ((uint32_t)__bfloat16_as_ushort(hy) << 16) | __bfloat16_as_ushort(hx);
}
// pack hi pair; compute lo (residual) pair
__device__ __forceinline__ void split_pack(float x, float y, uint32_t& hi, uint32_t& lo) {
    __nv_bfloat16 hx = __float2bfloat16_rn(x);
    __nv_bfloat16 hy = __float2bfloat16_rn(y);
    hi = ((uint32_t)__bfloat16_as_ushort(hy) << 16) | __bfloat16_as_ushort(hx);
    lo = pack_bf16x2(x - __bfloat162float(hx), y - __bfloat162float(hy));
}

// ---------------------------------------------------------------------------
// Kernel 0: split W (fp32 [D][HS] x3) into transposed bf16 hi/lo [3*HS][D]
// ---------------------------------------------------------------------------
__global__ void wsplit_kernel(const float* __restrict__ Wq,
                              const float* __restrict__ Wk,
                              const float* __restrict__ Wv)
{
    int idx = blockIdx.x * 256 + threadIdx.x;
    if (idx >= 3 * HS * D) return;
    int m = idx >> 16;
    int n = (idx >> 10) & 63;
    int k = idx & 1023;
    const float* W = (m == 0) ? Wq : (m == 1) ? Wk : Wv;
    float v = W[k * HS + n];
    __nv_bfloat16 hi = __float2bfloat16_rn(v);
    __nv_bfloat16 lo = __float2bfloat16_rn(v - __bfloat162float(hi));
    g_Whi[idx] = hi;
    g_Wlo[idx] = lo;
}

// ---------------------------------------------------------------------------
// Kernel 1: QKV projection via mma.sync bf16 (3x-bf16 split).
// Epilogue emits bf16 hi/lo Q,K,V directly (attn consumes bf16).
// ---------------------------------------------------------------------------
#define QPITCH 144
#define SMX_HI 0
#define SMX_LO (128 * QPITCH)
#define SMW_HI (2 * 128 * QPITCH)
#define SMW_LO (SMW_HI + 192 * QPITCH)
#define SM_QKV_TOTAL (SMW_LO + 192 * QPITCH)  // 92160

__global__ __launch_bounds__(512, 1)
void qkv_mma_kernel(const float* __restrict__ x,
                    const float* __restrict__ bq,
                    const float* __restrict__ bk,
                    const float* __restrict__ bv)
{
    extern __shared__ __align__(16) char smem[];
    const uint32_t sb = smem_u32(smem);
    const int t  = threadIdx.x;
    const int l  = t & 31;
    const int w  = t >> 5;
    const int wm = w >> 2;
    const int wn = w & 3;
    const int row0 = blockIdx.x * 128;

    float C[12][4];
#pragma unroll
    for (int i = 0; i < 12; i++)
#pragma unroll
        for (int j = 0; j < 4; j++) C[i][j] = 0.f;

    const uint32_t aoff = (uint32_t)((wm * 32 + (l & 15)) * QPITCH + (l >> 4) * 16);
    const uint32_t boff = (uint32_t)((wn * 48 + (l & 7)) * QPITCH + ((l >> 3) & 1) * 16);

    for (int ci = 0; ci < 16; ci++) {
        const int k0 = ci * 64;
        __syncthreads();

#pragma unroll
        for (int i = 0; i < 8; i++) {
            int p  = t + 512 * i;
            int r  = p >> 5;
            int cp = p & 31;
            float2 v = *(const float2*)&x[(size_t)(row0 + r) * D + k0 + 2 * cp];
            uint32_t hp, lp;
            split_pack(v.x, v.y, hp, lp);
            *(uint32_t*)(smem + SMX_HI + r * QPITCH + cp * 4) = hp;
            *(uint32_t*)(smem + SMX_LO + r * QPITCH + cp * 4) = lp;
        }
#pragma unroll
        for (int i = 0; i < 12; i++) {
            int p  = t + 512 * i;
            int r  = p >> 5;
            int kp = p & 31;
            uint32_t hp = *(const uint32_t*)&g_Whi[(size_t)r * D + k0 + 2 * kp];
            uint32_t lp = *(const uint32_t*)&g_Wlo[(size_t)r * D + k0 + 2 * kp];
            *(uint32_t*)(smem + SMW_HI + r * QPITCH + kp * 4) = hp;
            *(uint32_t*)(smem + SMW_LO + r * QPITCH + kp * 4) = lp;
        }
        __syncthreads();

#pragma unroll
        for (int ks = 0; ks < 4; ks++) {
            const uint32_t kso = ks * 32;
            uint32_t a[2][4], b[6][2];

            ldmatrix_x4(a[0], sb + SMX_HI + aoff + kso);
            ldmatrix_x4(a[1], sb + SMX_HI + aoff + 16 * QPITCH + kso);
#pragma unroll
            for (int nt = 0; nt < 6; nt++)
                ldmatrix_x2(b[nt], sb + SMW_HI + boff + nt * 8 * QPITCH + kso);
#pragma unroll
            for (int mt = 0; mt < 2; mt++)
#pragma unroll
                for (int nt = 0; nt < 6; nt++) mma_bf16(C[mt * 6 + nt], a[mt], b[nt]);
#pragma unroll
            for (int nt = 0; nt < 6; nt++)
                ldmatrix_x2(b[nt], sb + SMW_LO + boff + nt * 8 * QPITCH + kso);
#pragma unroll
            for (int mt = 0; mt < 2; mt++)
#pragma unroll
                for (int nt = 0; nt < 6; nt++) mma_bf16(C[mt * 6 + nt], a[mt], b[nt]);
            ldmatrix_x4(a[0], sb + SMX_LO + aoff + kso);
            ldmatrix_x4(a[1], sb + SMX_LO + aoff + 16 * QPITCH + kso);
#pragma unroll
            for (int nt = 0; nt < 6; nt++)
                ldmatrix_x2(b[nt], sb + SMW_HI + boff + nt * 8 * QPITCH + kso);
#pragma unroll
            for (int mt = 0; mt < 2; mt++)
#pragma unroll
                for (int nt = 0; nt < 6; nt++) mma_bf16(C[mt * 6 + nt], a[mt], b[nt]);
        }
    }

    // epilogue: write bf16 hi/lo of (C + bias)
#pragma unroll
    for (int nt = 0; nt < 6; nt++) {
        const int gn  = wn * 48 + nt * 8;
        const int mtx = gn >> 6;
        const float* bias = (mtx == 0) ? bq : (mtx == 1) ? bk : bv;
        __nv_bfloat16* dh = (mtx == 0) ? g_Qhi : (mtx == 1) ? g_Khi : g_Vhi;
        __nv_bfloat16* dl = (mtx == 0) ? g_Qlo : (mtx == 1) ? g_Klo : g_Vlo;
        const int cn = (gn & 63) + (l & 3) * 2;
        const float b0 = bias[cn], b1 = bias[cn + 1];
#pragma unroll
        for (int mt = 0; mt < 2; mt++) {
            const int r = row0 + wm * 32 + mt * 16 + (l >> 2);
            uint32_t hp, lp;
            split_pack(C[mt * 6 + nt][0] + b0, C[mt * 6 + nt][1] + b1, hp, lp);
            *(uint32_t*)&dh[(size_t)r * HS + cn] = hp;
            *(uint32_t*)&dl[(size_t)r * HS + cn] = lp;
            split_pack(C[mt * 6 + nt][2] + b0, C[mt * 6 + nt][3] + b1, hp, lp);
            *(uint32_t*)&dh[(size_t)(r + 8) * HS + cn] = hp;
            *(uint32_t*)&dl[(size_t)(r + 8) * HS + cn] = lp;
        }
    }
}

// ---------------------------------------------------------------------------
// Kernel 2: causal flash attention via mma.sync bf16, online softmax in regs.
// Grid (16, B), 128 threads (4 warps x m16 rows). Each CTA: q-tiles {x, 31-x}.
// QK^T: Qhi*Khi + Qhi*Klo + Qlo*Khi.  PV: Phi*Vhi + Phi*Vlo + Plo*Vhi.
// P passes from S C-fragments directly into A-fragments (no smem round trip).
// ---------------------------------------------------------------------------
#define KP 144                    // tile row pitch in bytes (64 bf16 + 8 pad)
#define SQH 0
#define SQL (64 * KP)             //  9216
#define SKH (2 * 64 * KP)         // 18432
#define SKL (3 * 64 * KP)         // 27648
#define SVH (4 * 64 * KP)         // 36864
#define SVL (5 * 64 * KP)         // 46080
#define SM_ATTN_TOTAL (6 * 64 * KP)  // 55296
#define NQT (T / 64)

__global__ __launch_bounds__(128, 1)
void attn_mma_kernel(float* __restrict__ out)
{
    extern __shared__ __align__(16) char smem[];
    const uint32_t sb = smem_u32(smem);
    const int t = threadIdx.x;
    const int l = t & 31;
    const int w = t >> 5;          // 0..3: q-rows w*16..+16
    const int b = blockIdx.y;

    // ldmatrix lane-address offsets
    const uint32_t aoff = (uint32_t)((w * 16 + (l & 15)) * KP + (l >> 4) * 16); // A (Q)
    const uint32_t boff = (uint32_t)(((l & 7)) * KP + ((l >> 3) & 1) * 16);     // B (K), + nt*8*KP + hc*32
    const uint32_t voff = (uint32_t)((l & 15) * KP);                            // B (V trans), + j*16*KP + nt*16

    for (int pass = 0; pass < 2; pass++) {
        const int qt = pass ? (NQT - 1 - (int)blockIdx.x) : (int)blockIdx.x;
        const int q0 = qt * 64;

        __syncthreads();   // protect Q smem from previous pass

        // ---- stage Q tile (hi/lo) ----
#pragma unroll
        for (int i = 0; i < 16; i++) {
            int p = t + 128 * i;       // 2048 u32 per array
            int r = p >> 5, c = p & 31;
            size_t g = ((size_t)b * T + q0 + r) * HS + 2 * c;
            *(uint32_t*)(smem + SQH + r * KP + c * 4) = *(const uint32_t*)&g_Qhi[g];
            *(uint32_t*)(smem + SQL + r * KP + c * 4) = *(const uint32_t*)&g_Qlo[g];
        }
        __syncthreads();

        // ---- Q fragments in registers (4 k-chunks x hi/lo) ----
        uint32_t Qh[4][4], Ql[4][4];
#pragma unroll
        for (int hc = 0; hc < 4; hc++) {
            ldmatrix_x4(Qh[hc], sb + SQH + aoff + hc * 32);
            ldmatrix_x4(Ql[hc], sb + SQL + aoff + hc * 32);
        }

        float O[8][4];
#pragma unroll
        for (int nt = 0; nt < 8; nt++)
#pragma unroll
            for (int j = 0; j < 4; j++) O[nt][j] = 0.f;
        float m0 = -1e30f, m1 = -1e30f, l0 = 0.f, l1 = 0.f;

        for (int kt = 0; kt <= qt; kt++) {
            __syncthreads();   // drain reads of previous K/V tiles
            // ---- stage K,V tiles (hi/lo), [kc][h] layout ----
#pragma unroll
            for (int i = 0; i < 16; i++) {
                int p = t + 128 * i;
                int r = p >> 5, c = p & 31;
                size_t g = ((size_t)b * T + kt * 64 + r) * HS + 2 * c;
                *(uint32_t*)(smem + SKH + r * KP + c * 4) = *(const uint32_t*)&g_Khi[g];
                *(uint32_t*)(smem + SKL + r * KP + c * 4) = *(const uint32_t*)&g_Klo[g];
                *(uint32_t*)(smem + SVH + r * KP + c * 4) = *(const uint32_t*)&g_Vhi[g];
                *(uint32_t*)(smem + SVL + r * KP + c * 4) = *(const uint32_t*)&g_Vlo[g];
            }
            __syncthreads();

            // ---- S = Q K^T (split x3) ----
            float S[8][4];
#pragma unroll
            for (int nt = 0; nt < 8; nt++)
#pragma unroll
                for (int j = 0; j < 4; j++) S[nt][j] = 0.f;

#pragma unroll
            for (int hc = 0; hc < 4; hc++) {
#pragma unroll
                for (int nt = 0; nt < 8; nt++) {
                    uint32_t kh[2], kl[2];
                    ldmatrix_x2(kh, sb + SKH + boff + nt * 8 * KP + hc * 32);
                    ldmatrix_x2(kl, sb + SKL + boff + nt * 8 * KP + hc * 32);
                    mma_bf16(S[nt], Qh[hc], kh);
                    mma_bf16(S[nt], Qh[hc], kl);
                    mma_bf16(S[nt], Ql[hc], kh);
                }
            }

            // ---- scale + causal mask ----
            const bool diag = (kt == qt);
            const int rl0 = w * 16 + (l >> 2);
#pragma unroll
            for (int nt = 0; nt < 8; nt++) {
                const int col = nt * 8 + (l & 3) * 2;
#pragma unroll
                for (int j = 0; j < 4; j++) {
                    float v = S[nt][j] * 0.125f;
                    int cc = col + (j & 1);
                    int rr = rl0 + ((j >> 1) << 3);
                    if (diag && cc > rr) v = -1e30f;
                    S[nt][j] = v;
                }
            }

            // ---- online softmax (2 rows per thread, shfl over 4-lane group) ----
            float mx0 = -1e30f, mx1 = -1e30f;
#pragma unroll
            for (int nt = 0; nt < 8; nt++) {
                mx0 = fmaxf(mx0, fmaxf(S[nt][0], S[nt][1]));
                mx1 = fmaxf(mx1, fmaxf(S[nt][2], S[nt][3]));
            }
            mx0 = fmaxf(mx0, __shfl_xor_sync(0xffffffffu, mx0, 1));
            mx0 = fmaxf(mx0, __shfl_xor_sync(0xffffffffu, mx0, 2));
            mx1 = fmaxf(mx1, __shfl_xor_sync(0xffffffffu, mx1, 1));
            mx1 = fmaxf(mx1, __shfl_xor_sync(0xffffffffu, mx1, 2));

            float mn0 = fmaxf(m0, mx0), mn1 = fmaxf(m1, mx1);
            float c0 = __expf(m0 - mn0), c1 = __expf(m1 - mn1);
            float s0 = 0.f, s1 = 0.f;
#pragma unroll
            for (int nt = 0; nt < 8; nt++) {
                S[nt][0] = __expf(S[nt][0] - mn0); s0 += S[nt][0];
                S[nt][1] = __expf(S[nt][1] - mn0); s0 += S[nt][1];
                S[nt][2] = __expf(S[nt][2] - mn1); s1 += S[nt][2];
                S[nt][3] = __expf(S[nt][3] - mn1); s1 += S[nt][3];
            }
            s0 += __shfl_xor_sync(0xffffffffu, s0, 1);
            s0 += __shfl_xor_sync(0xffffffffu, s0, 2);
            s1 += __shfl_xor_sync(0xffffffffu, s1, 1);
            s1 += __shfl_xor_sync(0xffffffffu, s1, 2);
            l0 = l0 * c0 + s0;  l1 = l1 * c1 + s1;
            m0 = mn0;  m1 = mn1;
#pragma unroll
            for (int nt = 0; nt < 8; nt++) {
                O[nt][0] *= c0; O[nt][1] *= c0; O[nt][2] *= c1; O[nt][3] *= c1;
            }

            // ---- pack P (C-frags -> A-frags, hi/lo split) ----
            uint32_t Ph[4][4], Pl[4][4];
#pragma unroll
            for (int j = 0; j < 4; j++) {
                split_pack(S[2 * j][0],     S[2 * j][1],     Ph[j][0], Pl[j][0]);
                split_pack(S[2 * j][2],     S[2 * j][3],     Ph[j][1], Pl[j][1]);
                split_pack(S[2 * j + 1][0], S[2 * j + 1][1], Ph[j][2], Pl[j][2]);
                split_pack(S[2 * j + 1][2], S[2 * j + 1][3], Ph[j][3], Pl[j][3]);
            }

            // ---- O += P V (split x3), V via trans-ldmatrix ----
#pragma unroll
            for (int nt = 0; nt < 8; nt++) {
#pragma unroll
                for (int j = 0; j < 4; j++) {
                    uint32_t vh[2], vl[2];
                    ldmatrix_x2_trans(vh, sb + SVH + voff + j * 16 * KP + nt * 16);
                    ldmatrix_x2_trans(vl, sb + SVL + voff + j * 16 * KP + nt * 16);
                    mma_bf16(O[nt], Ph[j], vh);
                    mma_bf16(O[nt], Ph[j], vl);
                    mma_bf16(O[nt], Pl[j], vh);
                }
            }
        }

        // ---- epilogue ----
        const float i0 = 1.0f / l0, i1 = 1.0f / l1;
        const size_t rg = (size_t)b * T + q0 + w * 16 + (l >> 2);
#pragma unroll
        for (int nt = 0; nt < 8; nt++) {
            const int col = nt * 8 + (l & 3) * 2;
            float2 v0 = { O[nt][0] * i0, O[nt][1] * i0 };
            float2 v1 = { O[nt][2] * i1, O[nt][3] * i1 };
            *(float2*)&out[rg * HS + col]       = v0;
            *(float2*)&out[(rg + 8) * HS + col] = v1;
        }
    }
}

// ---------------------------------------------------------------------------
extern "C" void kernel_launch(void* const* d_in, const int* in_sizes, int n_in,
                              void* d_out, int out_size)
{
    const float* x  = (const float*)d_in[0];
    const float* Wq = (const float*)d_in[1];
    const float* bq = (const float*)d_in[2];
    const float* Wk = (const float*)d_in[3];
    const float* bk = (const float*)d_in[4];
    const float* Wv = (const float*)d_in[5];
    const float* bv = (const float*)d_in[6];
    float* out = (float*)d_out;

    wsplit_kernel<<<(3 * HS * D + 255) / 256, 256>>>(Wq, Wk, Wv);

    cudaFuncSetAttribute(qkv_mma_kernel, cudaFuncAttributeMaxDynamicSharedMemorySize, SM_QKV_TOTAL);
    qkv_mma_kernel<<<BT / 128, 512, SM_QKV_TOTAL>>>(x, bq, bk, bv);

    cudaFuncSetAttribute(attn_mma_kernel, cudaFuncAttributeMaxDynamicSharedMemorySize, SM_ATTN_TOTAL);
    attn_mma_kernel<<<dim3(NQT / 2, B), 128, SM_ATTN_TOTAL>>>(out);
}